// round 1
// baseline (speedup 1.0000x reference)
#include <cuda_runtime.h>
#include <math.h>

// ---------------- problem constants ----------------
#define BB   16
#define TT   32
#define NN_  512
#define CC   128
#define HH   128
#define HLL  512
#define G4   (4*HLL)        // 2048
#define DD   (NN_*HH)       // 65536
#define TNH  ((long)TT*NN_*HH)   // 2,097,152  (per-batch stride)
#define EPSN 1e-5f

// ---------------- device scratch ----------------
__device__ float g_d[NN_];
__device__ float g_M[NN_*NN_];
__device__ float g_hw [BB*TT*NN_*HH];
__device__ float g_tmp[BB*TT*NN_*HH];
__device__ float g_h1 [BB*TT*NN_*HH];
__device__ float g_h2 [BB*TT*NN_*HH];
__device__ float g_Z0[(long)BB*TT*G4];
__device__ float g_Z1[(long)BB*TT*G4];
__device__ float g_y0[(long)BB*TT*HLL];
__device__ float g_WhhT0[HLL*G4];
__device__ float g_WhhT1[HLL*G4];
__device__ float g_hA0[BB*HLL], g_hB0[BB*HLL], g_c0[BB*HLL];
__device__ float g_hA1[BB*HLL], g_hB1[BB*HLL], g_c1[BB*HLL];

// ---------------- helpers ----------------
__device__ __forceinline__ float sigf(float x) { return 1.0f/(1.0f+expf(-x)); }

// ---------------- graph normalization matrix ----------------
__global__ void deg_kernel(const float* __restrict__ adj, float* __restrict__ d) {
    int i = blockIdx.x*blockDim.x + threadIdx.x;
    if (i < NN_) {
        float s = 1.0f;                       // self loop
        for (int j = 0; j < NN_; j++) s += adj[(long)j*NN_ + i];
        d[i] = rsqrtf(s);
    }
}
__global__ void buildM_kernel(const float* __restrict__ adj, const float* __restrict__ d,
                              float* __restrict__ M) {
    int idx = blockIdx.x*blockDim.x + threadIdx.x;
    if (idx < NN_*NN_) {
        int j = idx >> 9, i = idx & (NN_-1);
        float a = adj[idx] + (i == j ? 1.0f : 0.0f);
        M[idx] = d[j]*a*d[i];
    }
}

// ---------------- tiled GEMM: C = A(MxK) @ B(KxN) (+bias[n]), batched ----------------
// packed row-major, all dims divisible by tile sizes. grid: (N/64, M/64, batch)
__global__ void gemm_nn(const float* __restrict__ Ab, const float* __restrict__ Bb,
                        const float* __restrict__ biasb, float* __restrict__ Cb,
                        int M, int N, int K,
                        long sA, int modA, long sB, int modB,
                        long sBias, int modBias, long sC)
{
    int z = blockIdx.z;
    const float* A = Ab + (long)(z % modA) * sA;
    const float* B = Bb + (long)(z % modB) * sB;
    float* C = Cb + (long)z * sC;
    const float* bias = biasb ? biasb + (long)(z % modBias) * sBias : nullptr;

    __shared__ float As[16][68];   // As[k][m] transposed, padded for fp32x4 reads
    __shared__ float Bs[16][64];   // Bs[k][n]
    int tx = threadIdx.x, ty = threadIdx.y, tid = ty*16 + tx;
    int m0 = blockIdx.y*64, n0 = blockIdx.x*64;
    float acc[4][4] = {};

    for (int k0 = 0; k0 < K; k0 += 16) {
        #pragma unroll
        for (int i = 0; i < 4; i++) {
            int idx = tid + i*256;
            int r = idx >> 4, c = idx & 15;
            As[c][r] = A[(long)(m0 + r)*K + k0 + c];
        }
        #pragma unroll
        for (int i = 0; i < 4; i++) {
            int idx = tid + i*256;
            int r = idx >> 6, c = idx & 63;
            Bs[r][c] = B[(long)(k0 + r)*N + n0 + c];
        }
        __syncthreads();
        #pragma unroll
        for (int kk = 0; kk < 16; kk++) {
            float4 a4 = *(const float4*)&As[kk][ty*4];
            float4 b4 = *(const float4*)&Bs[kk][tx*4];
            float a[4] = {a4.x, a4.y, a4.z, a4.w};
            float b[4] = {b4.x, b4.y, b4.z, b4.w};
            #pragma unroll
            for (int i = 0; i < 4; i++)
                #pragma unroll
                for (int j = 0; j < 4; j++)
                    acc[i][j] += a[i]*b[j];
        }
        __syncthreads();
    }
    #pragma unroll
    for (int i = 0; i < 4; i++) {
        int m = m0 + ty*4 + i;
        #pragma unroll
        for (int j = 0; j < 4; j++) {
            int n = n0 + tx*4 + j;
            float v = acc[i][j];
            if (bias) v += bias[n];
            C[(long)m*N + n] = v;
        }
    }
}

// ---------------- tiled GEMM: C = A(MxK) @ B(NxK)^T + bias[n] ----------------
__global__ void gemm_nt(const float* __restrict__ A, const float* __restrict__ B,
                        const float* __restrict__ bias, float* __restrict__ C,
                        int M, int N, int K)
{
    __shared__ float As[16][68];   // As[k][m]
    __shared__ float Bs[16][68];   // Bs[k][n]
    int tx = threadIdx.x, ty = threadIdx.y, tid = ty*16 + tx;
    int m0 = blockIdx.y*64, n0 = blockIdx.x*64;
    float acc[4][4] = {};

    for (int k0 = 0; k0 < K; k0 += 16) {
        #pragma unroll
        for (int i = 0; i < 4; i++) {
            int idx = tid + i*256;
            int r = idx >> 4, c = idx & 15;
            As[c][r] = A[(long)(m0 + r)*K + k0 + c];
            Bs[c][r] = B[(long)(n0 + r)*K + k0 + c];
        }
        __syncthreads();
        #pragma unroll
        for (int kk = 0; kk < 16; kk++) {
            float4 a4 = *(const float4*)&As[kk][ty*4];
            float4 b4 = *(const float4*)&Bs[kk][tx*4];
            float a[4] = {a4.x, a4.y, a4.z, a4.w};
            float b[4] = {b4.x, b4.y, b4.z, b4.w};
            #pragma unroll
            for (int i = 0; i < 4; i++)
                #pragma unroll
                for (int j = 0; j < 4; j++)
                    acc[i][j] += a[i]*b[j];
        }
        __syncthreads();
    }
    #pragma unroll
    for (int i = 0; i < 4; i++) {
        int m = m0 + ty*4 + i;
        #pragma unroll
        for (int j = 0; j < 4; j++) {
            int n = n0 + tx*4 + j;
            C[(long)m*N + n] = acc[i][j] + bias[n];
        }
    }
}

// ---------------- GraphNorm + residual + ReLU (stats over batch dim) ----------------
__global__ void graphnorm_kernel(const float* __restrict__ hraw, const float* __restrict__ res,
                                 const float* __restrict__ w, const float* __restrict__ bias,
                                 const float* __restrict__ ms, float* __restrict__ out)
{
    long p = (long)blockIdx.x*blockDim.x + threadIdx.x;   // index over (t,n,h)
    if (p >= TNH) return;
    int h = (int)(p & (HH-1));
    float v[BB];
    float mean = 0.0f;
    #pragma unroll
    for (int b = 0; b < BB; b++) { v[b] = hraw[(long)b*TNH + p]; mean += v[b]; }
    mean *= (1.0f/BB);
    float msv = ms[h], var = 0.0f;
    #pragma unroll
    for (int b = 0; b < BB; b++) { v[b] -= msv*mean; var += v[b]*v[b]; }
    var *= (1.0f/BB);
    float inv = rsqrtf(var + EPSN);
    float wv = w[h]*inv, bv = bias[h];
    #pragma unroll
    for (int b = 0; b < BB; b++) {
        float r = wv*v[b] + bv + res[(long)b*TNH + p];
        out[(long)b*TNH + p] = fmaxf(r, 0.0f);
    }
}

// ---------------- 32x32 tiled transpose: out[c][r] = in[r][c] ----------------
__global__ void transpose_kernel(const float* __restrict__ in, float* __restrict__ out,
                                 int R, int Ccols)
{
    __shared__ float tile[32][33];
    int c0 = blockIdx.x*32, r0 = blockIdx.y*32;
    int tx = threadIdx.x, ty = threadIdx.y;
    #pragma unroll
    for (int i = 0; i < 32; i += 8)
        tile[ty+i][tx] = in[(long)(r0+ty+i)*Ccols + c0+tx];
    __syncthreads();
    #pragma unroll
    for (int i = 0; i < 32; i += 8)
        out[(long)(c0+ty+i)*R + r0+tx] = tile[tx][ty+i];
}

// ---------------- zero-init LSTM states ----------------
__global__ void zero_states_kernel(float* a, float* b, float* c, float* d) {
    int i = blockIdx.x*blockDim.x + threadIdx.x;
    if (i < BB*HLL) { a[i]=0.f; b[i]=0.f; c[i]=0.f; d[i]=0.f; }
}

// ---------------- one LSTM timestep (gates + state update fused) ----------------
// grid: (HLL/128, BB/4), block 128. Z already contains x@Wih^T + bih.
__global__ void lstm_step_kernel(const float* __restrict__ Z, int t,
                                 const float* __restrict__ WhhT,   // [HLL][4*HLL]
                                 const float* __restrict__ bhh,
                                 const float* __restrict__ h_in,
                                 float* __restrict__ h_out,
                                 float* __restrict__ c,
                                 float* __restrict__ y)
{
    __shared__ float sh[4][HLL];
    int b0 = blockIdx.y*4;
    int tid = threadIdx.x;
    for (int i = tid; i < 4*HLL; i += 128) {
        int bb = i >> 9, j = i & (HLL-1);
        sh[bb][j] = h_in[(b0+bb)*HLL + j];
    }
    __syncthreads();

    int m = blockIdx.x*128 + tid;
    float ai[4] = {}, af[4] = {}, ag[4] = {}, ao[4] = {};
    #pragma unroll 4
    for (int j = 0; j < HLL; j++) {
        const float* w = WhhT + (long)j*G4;
        float wi = w[m], wf = w[HLL+m], wg = w[2*HLL+m], wo = w[3*HLL+m];
        #pragma unroll
        for (int bb = 0; bb < 4; bb++) {
            float hv = sh[bb][j];
            ai[bb] += wi*hv; af[bb] += wf*hv; ag[bb] += wg*hv; ao[bb] += wo*hv;
        }
    }
    float bi = bhh[m], bf = bhh[HLL+m], bg = bhh[2*HLL+m], bo = bhh[3*HLL+m];
    #pragma unroll
    for (int bb = 0; bb < 4; bb++) {
        int b = b0 + bb;
        long zr = ((long)b*TT + t)*G4;
        float gi = sigf (Z[zr        + m] + ai[bb] + bi);
        float gf = sigf (Z[zr + HLL  + m] + af[bb] + bf);
        float gg = tanhf(Z[zr + 2*HLL+ m] + ag[bb] + bg);
        float go = sigf (Z[zr + 3*HLL+ m] + ao[bb] + bo);
        float cn = gf*c[b*HLL + m] + gi*gg;
        float hn = go*tanhf(cn);
        c[b*HLL + m] = cn;
        h_out[b*HLL + m] = hn;
        if (y) y[((long)b*TT + t)*HLL + m] = hn;
    }
}

// ---------------- final projection: out[b][o] = h[b]·Wp[o] + bp[o] ----------------
__global__ void proj_kernel(const float* __restrict__ h, const float* __restrict__ Wp,
                            const float* __restrict__ bp, float* __restrict__ out)
{
    int tid = threadIdx.x;                 // 128 = 16*8
    int b = tid >> 3, o = tid & 7;
    float s = bp[o];
    const float* wr = Wp + o*HLL;
    const float* hr = h  + b*HLL;
    for (int m = 0; m < HLL; m++) s += hr[m]*wr[m];
    out[b*8 + o] = s;
}

// ---------------- launch ----------------
extern "C" void kernel_launch(void* const* d_in, const int* in_sizes, int n_in,
                              void* d_out, int out_size)
{
    const float* x    = (const float*)d_in[0];
    const float* adj  = (const float*)d_in[1];
    const float* W1   = (const float*)d_in[2];
    const float* b1   = (const float*)d_in[3];
    const float* W2   = (const float*)d_in[4];
    const float* b2   = (const float*)d_in[5];
    const float* gn1w = (const float*)d_in[6];
    const float* gn1b = (const float*)d_in[7];
    const float* gn1m = (const float*)d_in[8];
    const float* gn2w = (const float*)d_in[9];
    const float* gn2b = (const float*)d_in[10];
    const float* gn2m = (const float*)d_in[11];
    const float* Wih0 = (const float*)d_in[12];
    const float* Whh0 = (const float*)d_in[13];
    const float* bih0 = (const float*)d_in[14];
    const float* bhh0 = (const float*)d_in[15];
    const float* Wih1 = (const float*)d_in[16];
    const float* Whh1 = (const float*)d_in[17];
    const float* bih1 = (const float*)d_in[18];
    const float* bhh1 = (const float*)d_in[19];
    const float* Wp   = (const float*)d_in[20];
    const float* bp   = (const float*)d_in[21];
    float* out = (float*)d_out;

    float *pD, *pM, *pHw, *pTmp, *pH1, *pH2, *pZ0, *pZ1, *pY0, *pT0, *pT1;
    float *pHA0, *pHB0, *pC0, *pHA1, *pHB1, *pC1;
    cudaGetSymbolAddress((void**)&pD,   g_d);
    cudaGetSymbolAddress((void**)&pM,   g_M);
    cudaGetSymbolAddress((void**)&pHw,  g_hw);
    cudaGetSymbolAddress((void**)&pTmp, g_tmp);
    cudaGetSymbolAddress((void**)&pH1,  g_h1);
    cudaGetSymbolAddress((void**)&pH2,  g_h2);
    cudaGetSymbolAddress((void**)&pZ0,  g_Z0);
    cudaGetSymbolAddress((void**)&pZ1,  g_Z1);
    cudaGetSymbolAddress((void**)&pY0,  g_y0);
    cudaGetSymbolAddress((void**)&pT0,  g_WhhT0);
    cudaGetSymbolAddress((void**)&pT1,  g_WhhT1);
    cudaGetSymbolAddress((void**)&pHA0, g_hA0);
    cudaGetSymbolAddress((void**)&pHB0, g_hB0);
    cudaGetSymbolAddress((void**)&pC0,  g_c0);
    cudaGetSymbolAddress((void**)&pHA1, g_hA1);
    cudaGetSymbolAddress((void**)&pHB1, g_hB1);
    cudaGetSymbolAddress((void**)&pC1,  g_c1);

    dim3 tb(16, 16);

    // normalization matrix M
    deg_kernel<<<2, 256>>>(adj, pD);
    buildM_kernel<<<(NN_*NN_)/256, 256>>>(adj, pD, pM);

    // transpose recurrent weights
    transpose_kernel<<<dim3(HLL/32, G4/32), dim3(32, 8)>>>(Whh0, pT0, G4, HLL);
    transpose_kernel<<<dim3(HLL/32, G4/32), dim3(32, 8)>>>(Whh1, pT1, G4, HLL);
    zero_states_kernel<<<(BB*HLL + 255)/256, 256>>>(pHA0, pC0, pHA1, pC1);

    const long sX = (long)NN_*HH;       // 65536 per (b,t)
    const int  BT = BB*TT;              // 512

    // ---- GCN layer 1 ----
    gemm_nn<<<dim3(HH/64, NN_/64, BT), tb>>>(x, W1, nullptr, pHw,
        NN_, HH, CC, sX, BT, (long)CC*HH, TT, 0, 1, sX);
    gemm_nn<<<dim3(HH/64, NN_/64, BT), tb>>>(pM, pHw, b1, pTmp,
        NN_, HH, NN_, 0, 1, sX, BT, HH, TT, sX);
    graphnorm_kernel<<<(int)(TNH/256), 256>>>(pTmp, x, gn1w, gn1b, gn1m, pH1);

    // ---- GCN layer 2 ----
    gemm_nn<<<dim3(HH/64, NN_/64, BT), tb>>>(pH1, W2, nullptr, pHw,
        NN_, HH, HH, sX, BT, (long)HH*HH, TT, 0, 1, sX);
    gemm_nn<<<dim3(HH/64, NN_/64, BT), tb>>>(pM, pHw, b2, pTmp,
        NN_, HH, NN_, 0, 1, sX, BT, HH, TT, sX);
    graphnorm_kernel<<<(int)(TNH/256), 256>>>(pTmp, pH1, gn2w, gn2b, gn2m, pH2);

    // ---- LSTM layer 0: input GEMM then 32 steps ----
    gemm_nt<<<dim3(G4/64, BT/64), tb>>>(pH2, Wih0, bih0, pZ0, BT, G4, DD);
    for (int t = 0; t < TT; t++) {
        float* hin  = (t & 1) ? pHB0 : pHA0;
        float* hout = (t & 1) ? pHA0 : pHB0;
        lstm_step_kernel<<<dim3(HLL/128, BB/4), 128>>>(pZ0, t, pT0, bhh0, hin, hout, pC0, pY0);
    }

    // ---- LSTM layer 1 ----
    gemm_nt<<<dim3(G4/64, BT/64), tb>>>(pY0, Wih1, bih1, pZ1, BT, G4, HLL);
    for (int t = 0; t < TT; t++) {
        float* hin  = (t & 1) ? pHB1 : pHA1;
        float* hout = (t & 1) ? pHA1 : pHB1;
        lstm_step_kernel<<<dim3(HLL/128, BB/4), 128>>>(pZ1, t, pT1, bhh1, hin, hout, pC1, nullptr);
    }

    // ---- projection (final h of layer 1 is in pHA1 after t=31) ----
    proj_kernel<<<1, 128>>>(pHA1, Wp, bp, out);
}

// round 2
// speedup vs baseline: 1.6764x; 1.6764x over previous
#include <cuda_runtime.h>
#include <math.h>
#include <stdint.h>

// ---------------- problem constants ----------------
#define BB   16
#define TT   32
#define NN_  512
#define CC   128
#define HH   128
#define HLL  512
#define G4   (4*HLL)        // 2048
#define DD   (NN_*HH)       // 65536
#define TNH  ((long)TT*NN_*HH)   // 2,097,152  (per-batch stride)
#define EPSN 1e-5f
#define SPLITK0 8

// ---------------- device scratch ----------------
__device__ float g_d[NN_];
__device__ float g_M[NN_*NN_];
__device__ float g_hw [BB*TT*NN_*HH];      // also reused as split-K partial buffer
__device__ float g_tmp[BB*TT*NN_*HH];
__device__ float g_h1 [BB*TT*NN_*HH];
__device__ float g_h2 [BB*TT*NN_*HH];
__device__ float g_Z0[(long)BB*TT*G4];
__device__ float g_Z1[(long)BB*TT*G4];
__device__ float g_y0[(long)BB*TT*HLL];
__device__ float g_WhhT0[HLL*G4];
__device__ float g_WhhT1[HLL*G4];
__device__ float g_hA0[BB*HLL], g_hB0[BB*HLL], g_c0[BB*HLL];
__device__ float g_hA1[BB*HLL], g_hB1[BB*HLL], g_c1[BB*HLL];

// ---------------- helpers ----------------
__device__ __forceinline__ float sigf(float x) { return 1.0f/(1.0f+expf(-x)); }
__device__ __forceinline__ uint32_t f2tf32(float f) {
    uint32_t u;
    asm("cvt.rna.tf32.f32 %0, %1;" : "=r"(u) : "f"(f));
    return u;
}

// ---------------- graph normalization matrix ----------------
__global__ void deg_kernel(const float* __restrict__ adj, float* __restrict__ d) {
    int i = blockIdx.x*blockDim.x + threadIdx.x;
    if (i < NN_) {
        float s = 1.0f;                       // self loop
        for (int j = 0; j < NN_; j++) s += adj[(long)j*NN_ + i];
        d[i] = rsqrtf(s);
    }
}
__global__ void buildM_kernel(const float* __restrict__ adj, const float* __restrict__ d,
                              float* __restrict__ M) {
    int idx = blockIdx.x*blockDim.x + threadIdx.x;
    if (idx < NN_*NN_) {
        int j = idx >> 9, i = idx & (NN_-1);
        float a = adj[idx] + (i == j ? 1.0f : 0.0f);
        M[idx] = d[j]*a*d[i];
    }
}

// ============================================================================
// TF32 tensor-core GEMM.
//   C[M,N] = A[M,K] @ B  (+ bias[n])
//   BT_=false: B is [K,N] row-major.   BT_=true: B is [N,K] row-major (B^T).
// CTA tile 128x128x16, 8 warps of 64x32, double-buffered smem, reg prefetch.
// blockIdx.z = batch*splitK + split. splitK>1 writes partials (bias must be null).
// ============================================================================
#define BM 128
#define BN 128
#define BK 16
#define ASTRIDE (BM+4)
#define BSTRIDE (BN+4)

template<bool BT_>
__global__ void __launch_bounds__(256, 2)
mma_gemm(const float* __restrict__ Ab, const float* __restrict__ Bb,
         const float* __restrict__ biasb, float* __restrict__ Cb,
         int M, int N, int K,
         long sA, int modA, long sB, int modB,
         long sBias, int modBias, long sC,
         int splitK, long sSplit)
{
    int z = blockIdx.z;
    int batch = z / splitK, split = z - batch*splitK;
    const float* A = Ab + (long)(batch % modA) * sA;
    const float* B = Bb + (long)(batch % modB) * sB;
    float* C = Cb + (long)batch * sC + (long)split * sSplit;
    const float* bias = biasb ? biasb + (long)(batch % modBias) * sBias : nullptr;

    int kchunk = K / splitK;
    int kbeg = split * kchunk;
    int nk = kchunk / BK;

    __shared__ uint32_t As[2][BK][ASTRIDE];
    __shared__ uint32_t Bs[2][BK][BSTRIDE];

    int tid = threadIdx.x;
    int lane = tid & 31;
    int warp = tid >> 5;
    int wm = (warp & 1) * 64;       // warp m offset in tile
    int wn = (warp >> 1) * 32;      // warp n offset in tile
    int m0 = blockIdx.y * BM;
    int n0 = blockIdx.x * BN;

    float acc[4][4][4];
    #pragma unroll
    for (int i = 0; i < 4; i++)
        #pragma unroll
        for (int j = 0; j < 4; j++)
            #pragma unroll
            for (int k = 0; k < 4; k++) acc[i][j][k] = 0.0f;

    // per-thread global-load coordinates
    // A: 512 float4 per tile -> 2/thread. m = idx>>2, kq = idx&3
    int a_m[2], a_kq[2];
    #pragma unroll
    for (int i = 0; i < 2; i++) { int idx = tid + i*256; a_m[i] = idx >> 2; a_kq[i] = idx & 3; }
    // B (BT): same pattern with n. B (NN): r = idx>>5, cq = idx&31
    int b_i0[2], b_i1[2];
    #pragma unroll
    for (int i = 0; i < 2; i++) {
        int idx = tid + i*256;
        if (BT_) { b_i0[i] = idx >> 2; b_i1[i] = idx & 3; }     // n, kq
        else     { b_i0[i] = idx >> 5; b_i1[i] = idx & 31; }    // r, cq
    }

    float4 ar[2], br[2];

    auto load_tile = [&](int kt) {
        int kg = kbeg + kt*BK;
        #pragma unroll
        for (int i = 0; i < 2; i++)
            ar[i] = *(const float4*)&A[(long)(m0 + a_m[i])*K + kg + a_kq[i]*4];
        #pragma unroll
        for (int i = 0; i < 2; i++) {
            if (BT_) br[i] = *(const float4*)&B[(long)(n0 + b_i0[i])*K + kg + b_i1[i]*4];
            else     br[i] = *(const float4*)&B[(long)(kg + b_i0[i])*N + n0 + b_i1[i]*4];
        }
    };
    auto store_tile = [&](int buf) {
        #pragma unroll
        for (int i = 0; i < 2; i++) {
            int m = a_m[i], kq = a_kq[i];
            As[buf][kq*4+0][m] = f2tf32(ar[i].x);
            As[buf][kq*4+1][m] = f2tf32(ar[i].y);
            As[buf][kq*4+2][m] = f2tf32(ar[i].z);
            As[buf][kq*4+3][m] = f2tf32(ar[i].w);
        }
        #pragma unroll
        for (int i = 0; i < 2; i++) {
            if (BT_) {
                int n = b_i0[i], kq = b_i1[i];
                Bs[buf][kq*4+0][n] = f2tf32(br[i].x);
                Bs[buf][kq*4+1][n] = f2tf32(br[i].y);
                Bs[buf][kq*4+2][n] = f2tf32(br[i].z);
                Bs[buf][kq*4+3][n] = f2tf32(br[i].w);
            } else {
                int r = b_i0[i], c = b_i1[i]*4;
                uint4 v;
                v.x = f2tf32(br[i].x); v.y = f2tf32(br[i].y);
                v.z = f2tf32(br[i].z); v.w = f2tf32(br[i].w);
                *(uint4*)&Bs[buf][r][c] = v;
            }
        }
    };

    load_tile(0);
    store_tile(0);
    __syncthreads();

    int lk = lane & 3, lg = lane >> 2;

    for (int kt = 0; kt < nk; kt++) {
        int cur = kt & 1;
        if (kt + 1 < nk) load_tile(kt + 1);

        #pragma unroll
        for (int ks = 0; ks < 2; ks++) {
            uint32_t af[4][4];
            #pragma unroll
            for (int mt = 0; mt < 4; mt++) {
                int mb = wm + mt*16;
                af[mt][0] = As[cur][ks*8 + lk    ][mb + lg    ];
                af[mt][1] = As[cur][ks*8 + lk    ][mb + lg + 8];
                af[mt][2] = As[cur][ks*8 + lk + 4][mb + lg    ];
                af[mt][3] = As[cur][ks*8 + lk + 4][mb + lg + 8];
            }
            uint32_t bf[4][2];
            #pragma unroll
            for (int nt = 0; nt < 4; nt++) {
                int nb = wn + nt*8;
                bf[nt][0] = Bs[cur][ks*8 + lk    ][nb + lg];
                bf[nt][1] = Bs[cur][ks*8 + lk + 4][nb + lg];
            }
            #pragma unroll
            for (int mt = 0; mt < 4; mt++)
                #pragma unroll
                for (int nt = 0; nt < 4; nt++) {
                    asm volatile(
                        "mma.sync.aligned.m16n8k8.row.col.f32.tf32.tf32.f32 "
                        "{%0,%1,%2,%3}, {%4,%5,%6,%7}, {%8,%9}, {%0,%1,%2,%3};"
                        : "+f"(acc[mt][nt][0]), "+f"(acc[mt][nt][1]),
                          "+f"(acc[mt][nt][2]), "+f"(acc[mt][nt][3])
                        : "r"(af[mt][0]), "r"(af[mt][1]), "r"(af[mt][2]), "r"(af[mt][3]),
                          "r"(bf[nt][0]), "r"(bf[nt][1]));
                }
        }

        if (kt + 1 < nk) {
            store_tile((kt + 1) & 1);
            __syncthreads();
        }
    }

    // epilogue
    #pragma unroll
    for (int nt = 0; nt < 4; nt++) {
        int c0 = n0 + wn + nt*8 + 2*lk;
        float bv0 = bias ? bias[c0] : 0.0f;
        float bv1 = bias ? bias[c0+1] : 0.0f;
        #pragma unroll
        for (int mt = 0; mt < 4; mt++) {
            int r = m0 + wm + mt*16 + lg;
            float2 v0 = make_float2(acc[mt][nt][0] + bv0, acc[mt][nt][1] + bv1);
            float2 v1 = make_float2(acc[mt][nt][2] + bv0, acc[mt][nt][3] + bv1);
            *(float2*)&C[(long)r*N + c0] = v0;
            *(float2*)&C[(long)(r+8)*N + c0] = v1;
        }
    }
}

// ---------------- split-K reduce + bias ----------------
__global__ void reduce_bias_kernel(const float* __restrict__ P, const float* __restrict__ bias,
                                   float* __restrict__ Z, long total, long stride, int splits)
{
    long idx = (long)blockIdx.x*blockDim.x + threadIdx.x;
    if (idx >= total) return;
    float s = bias[idx & (G4-1)];
    #pragma unroll 8
    for (int i = 0; i < splits; i++) s += P[(long)i*stride + idx];
    Z[idx] = s;
}

// ---------------- GraphNorm + residual + ReLU (stats over batch dim) ----------------
__global__ void graphnorm_kernel(const float* __restrict__ hraw, const float* __restrict__ res,
                                 const float* __restrict__ w, const float* __restrict__ bias,
                                 const float* __restrict__ ms, float* __restrict__ out)
{
    long p = (long)blockIdx.x*blockDim.x + threadIdx.x;   // index over (t,n,h)
    if (p >= TNH) return;
    int h = (int)(p & (HH-1));
    float v[BB];
    float mean = 0.0f;
    #pragma unroll
    for (int b = 0; b < BB; b++) { v[b] = hraw[(long)b*TNH + p]; mean += v[b]; }
    mean *= (1.0f/BB);
    float msv = ms[h], var = 0.0f;
    #pragma unroll
    for (int b = 0; b < BB; b++) { v[b] -= msv*mean; var += v[b]*v[b]; }
    var *= (1.0f/BB);
    float inv = rsqrtf(var + EPSN);
    float wv = w[h]*inv, bv = bias[h];
    #pragma unroll
    for (int b = 0; b < BB; b++) {
        float r = wv*v[b] + bv + res[(long)b*TNH + p];
        out[(long)b*TNH + p] = fmaxf(r, 0.0f);
    }
}

// ---------------- 32x32 tiled transpose: out[c][r] = in[r][c] ----------------
__global__ void transpose_kernel(const float* __restrict__ in, float* __restrict__ out,
                                 int R, int Ccols)
{
    __shared__ float tile[32][33];
    int c0 = blockIdx.x*32, r0 = blockIdx.y*32;
    int tx = threadIdx.x, ty = threadIdx.y;
    #pragma unroll
    for (int i = 0; i < 32; i += 8)
        tile[ty+i][tx] = in[(long)(r0+ty+i)*Ccols + c0+tx];
    __syncthreads();
    #pragma unroll
    for (int i = 0; i < 32; i += 8)
        out[(long)(c0+ty+i)*R + r0+tx] = tile[tx][ty+i];
}

// ---------------- zero-init LSTM states ----------------
__global__ void zero_states_kernel(float* a, float* b, float* c, float* d) {
    int i = blockIdx.x*blockDim.x + threadIdx.x;
    if (i < BB*HLL) { a[i]=0.f; b[i]=0.f; c[i]=0.f; d[i]=0.f; }
}

// ---------------- one LSTM timestep (gates + state update fused) ----------------
// grid: (HLL/128, BB/4), block 128. Z already contains x@Wih^T + bih.
__global__ void lstm_step_kernel(const float* __restrict__ Z, int t,
                                 const float* __restrict__ WhhT,   // [HLL][4*HLL]
                                 const float* __restrict__ bhh,
                                 const float* __restrict__ h_in,
                                 float* __restrict__ h_out,
                                 float* __restrict__ c,
                                 float* __restrict__ y)
{
    __shared__ float sh[4][HLL];
    int b0 = blockIdx.y*4;
    int tid = threadIdx.x;
    for (int i = tid; i < 4*HLL; i += 128) {
        int bb = i >> 9, j = i & (HLL-1);
        sh[bb][j] = h_in[(b0+bb)*HLL + j];
    }
    __syncthreads();

    int m = blockIdx.x*128 + tid;
    float ai[4] = {}, af[4] = {}, ag[4] = {}, ao[4] = {};
    #pragma unroll 4
    for (int j = 0; j < HLL; j++) {
        const float* w = WhhT + (long)j*G4;
        float wi = w[m], wf = w[HLL+m], wg = w[2*HLL+m], wo = w[3*HLL+m];
        #pragma unroll
        for (int bb = 0; bb < 4; bb++) {
            float hv = sh[bb][j];
            ai[bb] += wi*hv; af[bb] += wf*hv; ag[bb] += wg*hv; ao[bb] += wo*hv;
        }
    }
    float bi = bhh[m], bf = bhh[HLL+m], bg = bhh[2*HLL+m], bo = bhh[3*HLL+m];
    #pragma unroll
    for (int bb = 0; bb < 4; bb++) {
        int b = b0 + bb;
        long zr = ((long)b*TT + t)*G4;
        float gi = sigf (Z[zr        + m] + ai[bb] + bi);
        float gf = sigf (Z[zr + HLL  + m] + af[bb] + bf);
        float gg = tanhf(Z[zr + 2*HLL+ m] + ag[bb] + bg);
        float go = sigf (Z[zr + 3*HLL+ m] + ao[bb] + bo);
        float cn = gf*c[b*HLL + m] + gi*gg;
        float hn = go*tanhf(cn);
        c[b*HLL + m] = cn;
        h_out[b*HLL + m] = hn;
        if (y) y[((long)b*TT + t)*HLL + m] = hn;
    }
}

// ---------------- final projection ----------------
__global__ void proj_kernel(const float* __restrict__ h, const float* __restrict__ Wp,
                            const float* __restrict__ bp, float* __restrict__ out)
{
    int tid = threadIdx.x;                 // 128 = 16*8
    int b = tid >> 3, o = tid & 7;
    float s = bp[o];
    const float* wr = Wp + o*HLL;
    const float* hr = h  + b*HLL;
    for (int m = 0; m < HLL; m++) s += hr[m]*wr[m];
    out[b*8 + o] = s;
}

// ---------------- launch ----------------
extern "C" void kernel_launch(void* const* d_in, const int* in_sizes, int n_in,
                              void* d_out, int out_size)
{
    const float* x    = (const float*)d_in[0];
    const float* adj  = (const float*)d_in[1];
    const float* W1   = (const float*)d_in[2];
    const float* b1   = (const float*)d_in[3];
    const float* W2   = (const float*)d_in[4];
    const float* b2   = (const float*)d_in[5];
    const float* gn1w = (const float*)d_in[6];
    const float* gn1b = (const float*)d_in[7];
    const float* gn1m = (const float*)d_in[8];
    const float* gn2w = (const float*)d_in[9];
    const float* gn2b = (const float*)d_in[10];
    const float* gn2m = (const float*)d_in[11];
    const float* Wih0 = (const float*)d_in[12];
    const float* Whh0 = (const float*)d_in[13];
    const float* bih0 = (const float*)d_in[14];
    const float* bhh0 = (const float*)d_in[15];
    const float* Wih1 = (const float*)d_in[16];
    const float* Whh1 = (const float*)d_in[17];
    const float* bih1 = (const float*)d_in[18];
    const float* bhh1 = (const float*)d_in[19];
    const float* Wp   = (const float*)d_in[20];
    const float* bp   = (const float*)d_in[21];
    float* out = (float*)d_out;

    float *pD, *pM, *pHw, *pTmp, *pH1, *pH2, *pZ0, *pZ1, *pY0, *pT0, *pT1;
    float *pHA0, *pHB0, *pC0, *pHA1, *pHB1, *pC1;
    cudaGetSymbolAddress((void**)&pD,   g_d);
    cudaGetSymbolAddress((void**)&pM,   g_M);
    cudaGetSymbolAddress((void**)&pHw,  g_hw);
    cudaGetSymbolAddress((void**)&pTmp, g_tmp);
    cudaGetSymbolAddress((void**)&pH1,  g_h1);
    cudaGetSymbolAddress((void**)&pH2,  g_h2);
    cudaGetSymbolAddress((void**)&pZ0,  g_Z0);
    cudaGetSymbolAddress((void**)&pZ1,  g_Z1);
    cudaGetSymbolAddress((void**)&pY0,  g_y0);
    cudaGetSymbolAddress((void**)&pT0,  g_WhhT0);
    cudaGetSymbolAddress((void**)&pT1,  g_WhhT1);
    cudaGetSymbolAddress((void**)&pHA0, g_hA0);
    cudaGetSymbolAddress((void**)&pHB0, g_hB0);
    cudaGetSymbolAddress((void**)&pC0,  g_c0);
    cudaGetSymbolAddress((void**)&pHA1, g_hA1);
    cudaGetSymbolAddress((void**)&pHB1, g_hB1);
    cudaGetSymbolAddress((void**)&pC1,  g_c1);

    // normalization matrix M
    deg_kernel<<<2, 256>>>(adj, pD);
    buildM_kernel<<<(NN_*NN_)/256, 256>>>(adj, pD, pM);

    // transpose recurrent weights
    transpose_kernel<<<dim3(HLL/32, G4/32), dim3(32, 8)>>>(Whh0, pT0, G4, HLL);
    transpose_kernel<<<dim3(HLL/32, G4/32), dim3(32, 8)>>>(Whh1, pT1, G4, HLL);
    zero_states_kernel<<<(BB*HLL + 255)/256, 256>>>(pHA0, pC0, pHA1, pC1);

    const long sX = (long)NN_*HH;       // 65536 per (b,t)
    const int  BT = BB*TT;              // 512

    // ---- GCN layer 1 ----
    mma_gemm<false><<<dim3(HH/BN, NN_/BM, BT), 256>>>(x, W1, nullptr, pHw,
        NN_, HH, CC, sX, BT, (long)CC*HH, TT, 0, 1, sX, 1, 0);
    mma_gemm<false><<<dim3(HH/BN, NN_/BM, BT), 256>>>(pM, pHw, b1, pTmp,
        NN_, HH, NN_, 0, 1, sX, BT, HH, TT, sX, 1, 0);
    graphnorm_kernel<<<(int)(TNH/256), 256>>>(pTmp, x, gn1w, gn1b, gn1m, pH1);

    // ---- GCN layer 2 ----
    mma_gemm<false><<<dim3(HH/BN, NN_/BM, BT), 256>>>(pH1, W2, nullptr, pHw,
        NN_, HH, HH, sX, BT, (long)HH*HH, TT, 0, 1, sX, 1, 0);
    mma_gemm<false><<<dim3(HH/BN, NN_/BM, BT), 256>>>(pM, pHw, b2, pTmp,
        NN_, HH, NN_, 0, 1, sX, BT, HH, TT, sX, 1, 0);
    graphnorm_kernel<<<(int)(TNH/256), 256>>>(pTmp, pH1, gn2w, gn2b, gn2m, pH2);

    // ---- LSTM layer 0: big input GEMM (split-K=8 -> partials in pHw), reduce, 32 steps ----
    const long zTot = (long)BT*G4;      // 1,048,576
    mma_gemm<true><<<dim3(G4/BN, BT/BM, SPLITK0), 256>>>(pH2, Wih0, nullptr, pHw,
        BT, G4, DD, 0, 1, 0, 1, 0, 1, 0, SPLITK0, zTot);
    reduce_bias_kernel<<<(int)(zTot/256), 256>>>(pHw, bih0, pZ0, zTot, zTot, SPLITK0);
    for (int t = 0; t < TT; t++) {
        float* hin  = (t & 1) ? pHB0 : pHA0;
        float* hout = (t & 1) ? pHA0 : pHB0;
        lstm_step_kernel<<<dim3(HLL/128, BB/4), 128>>>(pZ0, t, pT0, bhh0, hin, hout, pC0, pY0);
    }

    // ---- LSTM layer 1 ----
    mma_gemm<true><<<dim3(G4/BN, BT/BM, 1), 256>>>(pY0, Wih1, bih1, pZ1,
        BT, G4, HLL, 0, 1, 0, 1, 0, 1, 0, 1, 0);
    for (int t = 0; t < TT; t++) {
        float* hin  = (t & 1) ? pHB1 : pHA1;
        float* hout = (t & 1) ? pHA1 : pHB1;
        lstm_step_kernel<<<dim3(HLL/128, BB/4), 128>>>(pZ1, t, pT1, bhh1, hin, hout, pC1, nullptr);
    }

    // ---- projection (final h of layer 1 is in pHA1 after t=31) ----
    proj_kernel<<<1, 128>>>(pHA1, Wp, bp, out);
}

// round 3
// speedup vs baseline: 3.9626x; 2.3638x over previous
#include <cuda_runtime.h>
#include <math.h>
#include <stdint.h>

// ---------------- problem constants ----------------
#define BB   16
#define TT   32
#define NN_  512
#define CC   128
#define HH   128
#define HLL  512
#define G4   (4*HLL)        // 2048
#define DD   (NN_*HH)       // 65536
#define TNH  ((long)TT*NN_*HH)   // 2,097,152  (per-batch stride)
#define EPSN 1e-5f
#define SPLITK0 8
#define LBLK 128
#define LTHR 256

// ---------------- device scratch ----------------
__device__ float g_d[NN_];
__device__ float g_M[NN_*NN_];
__device__ float g_hw [BB*TT*NN_*HH];      // also reused as split-K partial buffer
__device__ float g_tmp[BB*TT*NN_*HH];
__device__ float g_h1 [BB*TT*NN_*HH];
__device__ float g_h2 [BB*TT*NN_*HH];
__device__ float g_Z0[(long)BB*TT*G4];
__device__ float g_Z1[(long)BB*TT*G4];
__device__ float g_y0[(long)BB*TT*HLL];
__device__ float g_hA0[BB*HLL], g_hB0[BB*HLL];
__device__ float g_hA1[BB*HLL], g_hB1[BB*HLL];
__device__ unsigned g_bars[2];

// ---------------- helpers ----------------
__device__ __forceinline__ float sigf(float x) { return 1.0f/(1.0f+expf(-x)); }
__device__ __forceinline__ uint32_t f2tf32(float f) {
    uint32_t u;
    asm("cvt.rna.tf32.f32 %0, %1;" : "=r"(u) : "f"(f));
    return u;
}

// ---------------- graph normalization matrix ----------------
__global__ void deg_kernel(const float* __restrict__ adj, float* __restrict__ d) {
    int i = blockIdx.x*blockDim.x + threadIdx.x;
    if (i < NN_) {
        float s = 1.0f;                       // self loop
        for (int j = 0; j < NN_; j++) s += adj[(long)j*NN_ + i];
        d[i] = rsqrtf(s);
    }
}
__global__ void buildM_kernel(const float* __restrict__ adj, const float* __restrict__ d,
                              float* __restrict__ M) {
    int idx = blockIdx.x*blockDim.x + threadIdx.x;
    if (idx < NN_*NN_) {
        int j = idx >> 9, i = idx & (NN_-1);
        float a = adj[idx] + (i == j ? 1.0f : 0.0f);
        M[idx] = d[j]*a*d[i];
    }
}

// ============================================================================
// TF32 tensor-core GEMM (see R2). CTA tile 128x128x16, 8 warps of 64x32.
// ============================================================================
#define BM 128
#define BN 128
#define BK 16
#define ASTRIDE (BM+4)
#define BSTRIDE (BN+4)

template<bool BT_>
__global__ void __launch_bounds__(256, 2)
mma_gemm(const float* __restrict__ Ab, const float* __restrict__ Bb,
         const float* __restrict__ biasb, float* __restrict__ Cb,
         int M, int N, int K,
         long sA, int modA, long sB, int modB,
         long sBias, int modBias, long sC,
         int splitK, long sSplit)
{
    int z = blockIdx.z;
    int batch = z / splitK, split = z - batch*splitK;
    const float* A = Ab + (long)(batch % modA) * sA;
    const float* B = Bb + (long)(batch % modB) * sB;
    float* C = Cb + (long)batch * sC + (long)split * sSplit;
    const float* bias = biasb ? biasb + (long)(batch % modBias) * sBias : nullptr;

    int kchunk = K / splitK;
    int kbeg = split * kchunk;
    int nk = kchunk / BK;

    __shared__ uint32_t As[2][BK][ASTRIDE];
    __shared__ uint32_t Bs[2][BK][BSTRIDE];

    int tid = threadIdx.x;
    int lane = tid & 31;
    int warp = tid >> 5;
    int wm = (warp & 1) * 64;
    int wn = (warp >> 1) * 32;
    int m0 = blockIdx.y * BM;
    int n0 = blockIdx.x * BN;

    float acc[4][4][4];
    #pragma unroll
    for (int i = 0; i < 4; i++)
        #pragma unroll
        for (int j = 0; j < 4; j++)
            #pragma unroll
            for (int k = 0; k < 4; k++) acc[i][j][k] = 0.0f;

    int a_m[2], a_kq[2];
    #pragma unroll
    for (int i = 0; i < 2; i++) { int idx = tid + i*256; a_m[i] = idx >> 2; a_kq[i] = idx & 3; }
    int b_i0[2], b_i1[2];
    #pragma unroll
    for (int i = 0; i < 2; i++) {
        int idx = tid + i*256;
        if (BT_) { b_i0[i] = idx >> 2; b_i1[i] = idx & 3; }
        else     { b_i0[i] = idx >> 5; b_i1[i] = idx & 31; }
    }

    float4 ar[2], br[2];

    auto load_tile = [&](int kt) {
        int kg = kbeg + kt*BK;
        #pragma unroll
        for (int i = 0; i < 2; i++)
            ar[i] = *(const float4*)&A[(long)(m0 + a_m[i])*K + kg + a_kq[i]*4];
        #pragma unroll
        for (int i = 0; i < 2; i++) {
            if (BT_) br[i] = *(const float4*)&B[(long)(n0 + b_i0[i])*K + kg + b_i1[i]*4];
            else     br[i] = *(const float4*)&B[(long)(kg + b_i0[i])*N + n0 + b_i1[i]*4];
        }
    };
    auto store_tile = [&](int buf) {
        #pragma unroll
        for (int i = 0; i < 2; i++) {
            int m = a_m[i], kq = a_kq[i];
            As[buf][kq*4+0][m] = f2tf32(ar[i].x);
            As[buf][kq*4+1][m] = f2tf32(ar[i].y);
            As[buf][kq*4+2][m] = f2tf32(ar[i].z);
            As[buf][kq*4+3][m] = f2tf32(ar[i].w);
        }
        #pragma unroll
        for (int i = 0; i < 2; i++) {
            if (BT_) {
                int n = b_i0[i], kq = b_i1[i];
                Bs[buf][kq*4+0][n] = f2tf32(br[i].x);
                Bs[buf][kq*4+1][n] = f2tf32(br[i].y);
                Bs[buf][kq*4+2][n] = f2tf32(br[i].z);
                Bs[buf][kq*4+3][n] = f2tf32(br[i].w);
            } else {
                int r = b_i0[i], c = b_i1[i]*4;
                uint4 v;
                v.x = f2tf32(br[i].x); v.y = f2tf32(br[i].y);
                v.z = f2tf32(br[i].z); v.w = f2tf32(br[i].w);
                *(uint4*)&Bs[buf][r][c] = v;
            }
        }
    };

    load_tile(0);
    store_tile(0);
    __syncthreads();

    int lk = lane & 3, lg = lane >> 2;

    for (int kt = 0; kt < nk; kt++) {
        int cur = kt & 1;
        if (kt + 1 < nk) load_tile(kt + 1);

        #pragma unroll
        for (int ks = 0; ks < 2; ks++) {
            uint32_t af[4][4];
            #pragma unroll
            for (int mt = 0; mt < 4; mt++) {
                int mb = wm + mt*16;
                af[mt][0] = As[cur][ks*8 + lk    ][mb + lg    ];
                af[mt][1] = As[cur][ks*8 + lk    ][mb + lg + 8];
                af[mt][2] = As[cur][ks*8 + lk + 4][mb + lg    ];
                af[mt][3] = As[cur][ks*8 + lk + 4][mb + lg + 8];
            }
            uint32_t bf[4][2];
            #pragma unroll
            for (int nt = 0; nt < 4; nt++) {
                int nb = wn + nt*8;
                bf[nt][0] = Bs[cur][ks*8 + lk    ][nb + lg];
                bf[nt][1] = Bs[cur][ks*8 + lk + 4][nb + lg];
            }
            #pragma unroll
            for (int mt = 0; mt < 4; mt++)
                #pragma unroll
                for (int nt = 0; nt < 4; nt++) {
                    asm volatile(
                        "mma.sync.aligned.m16n8k8.row.col.f32.tf32.tf32.f32 "
                        "{%0,%1,%2,%3}, {%4,%5,%6,%7}, {%8,%9}, {%0,%1,%2,%3};"
                        : "+f"(acc[mt][nt][0]), "+f"(acc[mt][nt][1]),
                          "+f"(acc[mt][nt][2]), "+f"(acc[mt][nt][3])
                        : "r"(af[mt][0]), "r"(af[mt][1]), "r"(af[mt][2]), "r"(af[mt][3]),
                          "r"(bf[nt][0]), "r"(bf[nt][1]));
                }
        }

        if (kt + 1 < nk) {
            store_tile((kt + 1) & 1);
            __syncthreads();
        }
    }

    #pragma unroll
    for (int nt = 0; nt < 4; nt++) {
        int c0 = n0 + wn + nt*8 + 2*lk;
        float bv0 = bias ? bias[c0] : 0.0f;
        float bv1 = bias ? bias[c0+1] : 0.0f;
        #pragma unroll
        for (int mt = 0; mt < 4; mt++) {
            int r = m0 + wm + mt*16 + lg;
            float2 v0 = make_float2(acc[mt][nt][0] + bv0, acc[mt][nt][1] + bv1);
            float2 v1 = make_float2(acc[mt][nt][2] + bv0, acc[mt][nt][3] + bv1);
            *(float2*)&C[(long)r*N + c0] = v0;
            *(float2*)&C[(long)(r+8)*N + c0] = v1;
        }
    }
}

// ---------------- split-K reduce + bias ----------------
__global__ void reduce_bias_kernel(const float* __restrict__ P, const float* __restrict__ bias,
                                   float* __restrict__ Z, long total, long stride, int splits)
{
    long idx = (long)blockIdx.x*blockDim.x + threadIdx.x;
    if (idx >= total) return;
    float s = bias[idx & (G4-1)];
    #pragma unroll 8
    for (int i = 0; i < splits; i++) s += P[(long)i*stride + idx];
    Z[idx] = s;
}

// ---------------- GraphNorm + residual + ReLU ----------------
__global__ void graphnorm_kernel(const float* __restrict__ hraw, const float* __restrict__ res,
                                 const float* __restrict__ w, const float* __restrict__ bias,
                                 const float* __restrict__ ms, float* __restrict__ out)
{
    long p = (long)blockIdx.x*blockDim.x + threadIdx.x;
    if (p >= TNH) return;
    int h = (int)(p & (HH-1));
    float v[BB];
    float mean = 0.0f;
    #pragma unroll
    for (int b = 0; b < BB; b++) { v[b] = hraw[(long)b*TNH + p]; mean += v[b]; }
    mean *= (1.0f/BB);
    float msv = ms[h], var = 0.0f;
    #pragma unroll
    for (int b = 0; b < BB; b++) { v[b] -= msv*mean; var += v[b]*v[b]; }
    var *= (1.0f/BB);
    float inv = rsqrtf(var + EPSN);
    float wv = w[h]*inv, bv = bias[h];
    #pragma unroll
    for (int b = 0; b < BB; b++) {
        float r = wv*v[b] + bv + res[(long)b*TNH + p];
        out[(long)b*TNH + p] = fmaxf(r, 0.0f);
    }
}

// ---------------- zero barrier counters ----------------
__global__ void zero_bars_kernel(unsigned* bars) {
    if (threadIdx.x < 2) bars[threadIdx.x] = 0u;
}

// ============================================================================
// Persistent LSTM layer: 32 timesteps in one kernel. 128 blocks x 256 thr.
// Whh rows held in registers across all steps (32 floats/thread). Software
// grid barrier per step. c-state in registers of the 64 update threads.
// Block blk owns mh range [4*blk, 4*blk+4). Column c = gate*4 + mh_local.
// Thread t: c = t&15, sub = t>>4 (j-chunk of 32).
// ============================================================================
template<bool WRITE_Y>
__global__ void __launch_bounds__(LTHR, 1)
lstm_persistent(const float* __restrict__ Z,      // [BB][TT][G4]  (x@Wih^T + bih)
                const float* __restrict__ Whh,    // [G4][HLL] row-major
                const float* __restrict__ bhh,    // [G4]
                float* __restrict__ bufA, float* __restrict__ bufB,  // [BB][HLL]
                float* __restrict__ y,            // [BB][TT][HLL] or null
                unsigned* __restrict__ bar)
{
    __shared__ float hs[HLL][BB];          // 32 KB, hs[j][b]
    __shared__ float red[8*16*17];         // 8.5 KB, (warp*16+c)*17 + b
    __shared__ float gsum[16*16];          // [c][b]

    const int t = threadIdx.x;
    const int blk = blockIdx.x;
    const int c = t & 15, sub = t >> 4;
    const int warp = t >> 5;
    const int mh_local = c & 3, gate = c >> 2;
    const int m = gate*HLL + blk*4 + mh_local;

    // ---- one-time: weights into registers ----
    float w[32];
    {
        const float* wr = Whh + (long)m*HLL + sub*32;
        #pragma unroll
        for (int j = 0; j < 32; j++) w[j] = wr[j];
    }

    // ---- update-thread persistent state ----
    const int ub = t & 15;                 // batch for update threads (t<64)
    const int uml = (t >> 4) & 3;
    const int umh = blk*4 + uml;
    float creg = 0.0f;
    float bi = 0.f, bf = 0.f, bg = 0.f, bo = 0.f;
    if (t < 64) {
        bi = bhh[0*HLL + umh]; bf = bhh[1*HLL + umh];
        bg = bhh[2*HLL + umh]; bo = bhh[3*HLL + umh];
    }

    // h0 = 0
    for (int i = t; i < HLL*BB; i += LTHR) (&hs[0][0])[i] = 0.0f;
    __syncthreads();

    unsigned target = 0;

    for (int step = 0; step < TT; step++) {
        // prefetch Z for the update phase
        float zi = 0.f, zf = 0.f, zg = 0.f, zo = 0.f;
        if (t < 64) {
            long zb = ((long)ub*TT + step)*G4;
            zi = Z[zb + 0*HLL + umh]; zf = Z[zb + 1*HLL + umh];
            zg = Z[zb + 2*HLL + umh]; zo = Z[zb + 3*HLL + umh];
        }

        // ---- matvec partials: acc[b] = sum_{j in chunk} w[j]*h[b][j] ----
        float acc[BB];
        #pragma unroll
        for (int b = 0; b < BB; b++) acc[b] = 0.0f;
        #pragma unroll
        for (int j = 0; j < 32; j++) {
            float wv = w[j];
            const float* hr = &hs[sub*32 + j][0];
            #pragma unroll
            for (int b = 0; b < BB; b += 4) {
                float4 h4 = *(const float4*)&hr[b];
                acc[b+0] += wv*h4.x; acc[b+1] += wv*h4.y;
                acc[b+2] += wv*h4.z; acc[b+3] += wv*h4.w;
            }
        }
        // combine sub-pairs within warp (lane L gets lane L+16's partial)
        #pragma unroll
        for (int b = 0; b < BB; b++)
            acc[b] += __shfl_down_sync(0xffffffffu, acc[b], 16);
        if ((t & 31) < 16) {
            float* rp = &red[(warp*16 + c)*17];
            #pragma unroll
            for (int b = 0; b < BB; b++) rp[b] = acc[b];
        }
        __syncthreads();
        // final reduce over 8 warps: thread (c2 = t&15, b2 = t>>4)
        {
            int c2 = t & 15, b2 = t >> 4;
            float s = 0.0f;
            #pragma unroll
            for (int s2 = 0; s2 < 8; s2++) s += red[(s2*16 + c2)*17 + b2];
            gsum[c2*16 + b2] = s;
        }
        __syncthreads();

        // ---- gate nonlinearity + state update (64 threads) ----
        if (t < 64) {
            float gi = sigf (zi + gsum[(0*4+uml)*16 + ub] + bi);
            float gf = sigf (zf + gsum[(1*4+uml)*16 + ub] + bf);
            float gg = tanhf(zg + gsum[(2*4+uml)*16 + ub] + bg);
            float go = sigf (zo + gsum[(3*4+uml)*16 + ub] + bo);
            creg = gf*creg + gi*gg;
            float hn = go*tanhf(creg);
            float* hout = ((step+1) & 1) ? bufB : bufA;
            hout[ub*HLL + umh] = hn;
            if (WRITE_Y) y[((long)ub*TT + step)*HLL + umh] = hn;
            __threadfence();
        }
        __syncthreads();

        // ---- grid barrier ----
        target += LBLK;
        if (t == 0) {
            atomicAdd(bar, 1u);
            while (*(volatile unsigned*)bar < target) { }
        }
        __syncthreads();
        __threadfence();

        // ---- reload h into smem for next step ----
        if (step + 1 < TT) {
            const float* hin = ((step+1) & 1) ? bufB : bufA;
            for (int i = t; i < BB*HLL; i += LTHR) {
                int b = i >> 9, j = i & (HLL-1);
                hs[j][b] = hin[i];
            }
            __syncthreads();
        }
    }
}

// ---------------- final projection ----------------
__global__ void proj_kernel(const float* __restrict__ h, const float* __restrict__ Wp,
                            const float* __restrict__ bp, float* __restrict__ out)
{
    int tid = threadIdx.x;                 // 128 = 16*8
    int b = tid >> 3, o = tid & 7;
    float s = bp[o];
    const float* wr = Wp + o*HLL;
    const float* hr = h  + b*HLL;
    for (int m = 0; m < HLL; m++) s += hr[m]*wr[m];
    out[b*8 + o] = s;
}

// ---------------- launch ----------------
extern "C" void kernel_launch(void* const* d_in, const int* in_sizes, int n_in,
                              void* d_out, int out_size)
{
    const float* x    = (const float*)d_in[0];
    const float* adj  = (const float*)d_in[1];
    const float* W1   = (const float*)d_in[2];
    const float* b1   = (const float*)d_in[3];
    const float* W2   = (const float*)d_in[4];
    const float* b2   = (const float*)d_in[5];
    const float* gn1w = (const float*)d_in[6];
    const float* gn1b = (const float*)d_in[7];
    const float* gn1m = (const float*)d_in[8];
    const float* gn2w = (const float*)d_in[9];
    const float* gn2b = (const float*)d_in[10];
    const float* gn2m = (const float*)d_in[11];
    const float* Wih0 = (const float*)d_in[12];
    const float* Whh0 = (const float*)d_in[13];
    const float* bih0 = (const float*)d_in[14];
    const float* bhh0 = (const float*)d_in[15];
    const float* Wih1 = (const float*)d_in[16];
    const float* Whh1 = (const float*)d_in[17];
    const float* bih1 = (const float*)d_in[18];
    const float* bhh1 = (const float*)d_in[19];
    const float* Wp   = (const float*)d_in[20];
    const float* bp   = (const float*)d_in[21];
    float* out = (float*)d_out;

    float *pM, *pD, *pHw, *pTmp, *pH1, *pH2, *pZ0, *pZ1, *pY0;
    float *pHA0, *pHB0, *pHA1, *pHB1;
    unsigned* pBars;
    cudaGetSymbolAddress((void**)&pD,   g_d);
    cudaGetSymbolAddress((void**)&pM,   g_M);
    cudaGetSymbolAddress((void**)&pHw,  g_hw);
    cudaGetSymbolAddress((void**)&pTmp, g_tmp);
    cudaGetSymbolAddress((void**)&pH1,  g_h1);
    cudaGetSymbolAddress((void**)&pH2,  g_h2);
    cudaGetSymbolAddress((void**)&pZ0,  g_Z0);
    cudaGetSymbolAddress((void**)&pZ1,  g_Z1);
    cudaGetSymbolAddress((void**)&pY0,  g_y0);
    cudaGetSymbolAddress((void**)&pHA0, g_hA0);
    cudaGetSymbolAddress((void**)&pHB0, g_hB0);
    cudaGetSymbolAddress((void**)&pHA1, g_hA1);
    cudaGetSymbolAddress((void**)&pHB1, g_hB1);
    cudaGetSymbolAddress((void**)&pBars, g_bars);

    // normalization matrix M + barrier reset
    deg_kernel<<<2, 256>>>(adj, pD);
    buildM_kernel<<<(NN_*NN_)/256, 256>>>(adj, pD, pM);
    zero_bars_kernel<<<1, 32>>>(pBars);

    const long sX = (long)NN_*HH;       // 65536 per (b,t)
    const int  BT = BB*TT;              // 512

    // ---- GCN layer 1 ----
    mma_gemm<false><<<dim3(HH/BN, NN_/BM, BT), 256>>>(x, W1, nullptr, pHw,
        NN_, HH, CC, sX, BT, (long)CC*HH, TT, 0, 1, sX, 1, 0);
    mma_gemm<false><<<dim3(HH/BN, NN_/BM, BT), 256>>>(pM, pHw, b1, pTmp,
        NN_, HH, NN_, 0, 1, sX, BT, HH, TT, sX, 1, 0);
    graphnorm_kernel<<<(int)(TNH/256), 256>>>(pTmp, x, gn1w, gn1b, gn1m, pH1);

    // ---- GCN layer 2 ----
    mma_gemm<false><<<dim3(HH/BN, NN_/BM, BT), 256>>>(pH1, W2, nullptr, pHw,
        NN_, HH, HH, sX, BT, (long)HH*HH, TT, 0, 1, sX, 1, 0);
    mma_gemm<false><<<dim3(HH/BN, NN_/BM, BT), 256>>>(pM, pHw, b2, pTmp,
        NN_, HH, NN_, 0, 1, sX, BT, HH, TT, sX, 1, 0);
    graphnorm_kernel<<<(int)(TNH/256), 256>>>(pTmp, pH1, gn2w, gn2b, gn2m, pH2);

    // ---- LSTM layer 0: big input GEMM (split-K=8), reduce, persistent recurrence ----
    const long zTot = (long)BT*G4;      // 1,048,576
    mma_gemm<true><<<dim3(G4/BN, BT/BM, SPLITK0), 256>>>(pH2, Wih0, nullptr, pHw,
        BT, G4, DD, 0, 1, 0, 1, 0, 1, 0, SPLITK0, zTot);
    reduce_bias_kernel<<<(int)(zTot/256), 256>>>(pHw, bih0, pZ0, zTot, zTot, SPLITK0);
    lstm_persistent<true><<<LBLK, LTHR>>>(pZ0, Whh0, bhh0, pHA0, pHB0, pY0, pBars + 0);

    // ---- LSTM layer 1 ----
    mma_gemm<true><<<dim3(G4/BN, BT/BM, 1), 256>>>(pY0, Wih1, bih1, pZ1,
        BT, G4, HLL, 0, 1, 0, 1, 0, 1, 0, 1, 0);
    lstm_persistent<false><<<LBLK, LTHR>>>(pZ1, Whh1, bhh1, pHA1, pHB1, nullptr, pBars + 1);

    // ---- projection (final h of layer 1 lands in bufA) ----
    proj_kernel<<<1, 128>>>(pHA1, Wp, bp, out);
}